// round 7
// baseline (speedup 1.0000x reference)
#include <cuda_runtime.h>
#include <cuda_bf16.h>

#define CRF_B 512
#define CRF_T 1024
#define CRF_K 64
#define WPB 4   // warps per block

__device__ float g_per_batch[CRF_B];

__global__ void __launch_bounds__(32 * WPB, 1) crf_forward_kernel(
    const float* __restrict__ emissions,       // [B, T, K] f32
    const float* __restrict__ transitions,     // [K, K] f32
    const float* __restrict__ start_t,         // [K] f32
    const float* __restrict__ end_t,           // [K] f32
    const int* __restrict__ tags,              // [B, T] int32
    const int* __restrict__ mask)              // [B, T] int32
{
    __shared__ __align__(16) float pbuf[WPB][2][CRF_K];

    const int warp = threadIdx.x >> 5;
    const int lane = threadIdx.x & 31;
    const int b = blockIdx.x * WPB + warp;
    const unsigned FULL = 0xffffffffu;

    const float* em = emissions + (size_t)b * CRF_T * CRF_K;
    const int* tg = tags + (size_t)b * CRF_T;
    const int* mk = mask + (size_t)b * CRF_T;

    // ---------------- numerator (gold-path score) ----------------
    float part = 0.f;
    int cnt = 0;
    for (int t = lane; t < CRF_T; t += 32) {
        int m = (mk[t] != 0) ? 1 : 0;
        cnt += m;
        if (t > 0 && m) {
            int tag  = tg[t];
            int ptag = tg[t - 1];
            part += em[t * CRF_K + tag] + transitions[ptag * CRF_K + tag];
        }
    }
    #pragma unroll
    for (int off = 16; off; off >>= 1) {
        part += __shfl_xor_sync(FULL, part, off);
        cnt  += __shfl_xor_sync(FULL, cnt,  off);
    }
    float numer = 0.f;
    if (lane == 0) {
        int tag0 = tg[0];
        numer = part + em[tag0] + start_t[tag0];
        numer += end_t[tg[cnt - 1]];
    }

    // ------- E = exp(transitions), 2 columns per thread in registers -------
    float E0[CRF_K];
    float E1[CRF_K];
    #pragma unroll
    for (int i = 0; i < CRF_K; i++) {
        E0[i] = __expf(transitions[i * CRF_K + lane]);
        E1[i] = __expf(transitions[i * CRF_K + lane + 32]);
    }

    // ---------------- init: p = exp(alpha0 - ref0), C = ref0 ----------------
    float a0 = em[lane]      + start_t[lane];
    float a1 = em[lane + 32] + start_t[lane + 32];
    float r0 = fmaxf(a0, a1);
    #pragma unroll
    for (int off = 16; off; off >>= 1)
        r0 = fmaxf(r0, __shfl_xor_sync(FULL, r0, off));
    float p0 = __expf(a0 - r0);
    float p1 = __expf(a1 - r0);
    float C = r0;

    // ------- distance-4 pipeline of (w, delta, mask) for steps t..t+3 -------
    // slot q holds step s with s & 3 == q. w = exp(e - delta), delta = warp-max e.
    float w0p[4], w1p[4], dpp[4];
    int   mpp[4];
    #pragma unroll
    for (int q = 1; q <= 4; q++) {
        float e0 = em[q * CRF_K + lane];
        float e1 = em[q * CRF_K + 32 + lane];
        float dm = fmaxf(e0, e1);
        #pragma unroll
        for (int off = 16; off; off >>= 1)
            dm = fmaxf(dm, __shfl_xor_sync(FULL, dm, off));
        int s = q & 3;
        dpp[s] = dm;
        w0p[s] = __expf(e0 - dm);
        w1p[s] = __expf(e1 - dm);
        mpp[s] = mk[q];
    }

    // seed p buffer for t = 1
    {
        float* pb0 = pbuf[warp][0];
        pb0[lane] = p0;
        pb0[lane + 32] = p1;
        __syncwarp();
    }

    for (int t = 1; t < CRF_T; ++t) {
        const int slot = t & 3;
        // consume this step's pipeline entry
        float wc0 = w0p[slot], wc1 = w1p[slot], dc = dpp[slot];
        int mc = mpp[slot];

        // refill slot with step t+4 (loads + exp + shfl-max, all off-chain)
        {
            float e0 = 0.f, e1 = 0.f;
            int m = 0;
            if (t + 4 < CRF_T) {
                e0 = em[(t + 4) * CRF_K + lane];
                e1 = em[(t + 4) * CRF_K + 32 + lane];
                m  = mk[t + 4];
            }
            float dm = fmaxf(e0, e1);
            #pragma unroll
            for (int off = 16; off; off >>= 1)
                dm = fmaxf(dm, __shfl_xor_sync(FULL, dm, off));
            dpp[slot] = dm;
            w0p[slot] = __expf(e0 - dm);
            w1p[slot] = __expf(e1 - dm);
            mpp[slot] = m;
        }

        // matvec: s_j = sum_i p_i * E[i][j]
        const float4* pv4 = (const float4*)pbuf[warp][(t - 1) & 1];
        float s0a = 0.f, s0b = 0.f, s1a = 0.f, s1b = 0.f;
        #pragma unroll
        for (int q = 0; q < 16; q++) {
            float4 v = pv4[q];          // broadcast LDS.128, conflict-free
            int i = q * 4;
            s0a = fmaf(v.x, E0[i],     s0a);
            s0b = fmaf(v.y, E0[i + 1], s0b);
            s0a = fmaf(v.z, E0[i + 2], s0a);
            s0b = fmaf(v.w, E0[i + 3], s0b);
            s1a = fmaf(v.x, E1[i],     s1a);
            s1b = fmaf(v.y, E1[i + 1], s1b);
            s1a = fmaf(v.z, E1[i + 2], s1a);
            s1b = fmaf(v.w, E1[i + 3], s1b);
        }

        // exp-space update: p' = s * w, C += delta (masked)
        bool mm = (mc != 0);
        float np0 = (s0a + s0b) * wc0;
        float np1 = (s1a + s1b) * wc1;
        p0 = mm ? np0 : p0;
        p1 = mm ? np1 : p1;
        C  = mm ? C + dc : C;

        // periodic renormalization (keeps p in fp32 range)
        if ((t & 15) == 0) {
            float r = __shfl_sync(FULL, p0, 0);
            C += __logf(r);
            float inv = __fdividef(1.0f, r);
            p0 *= inv;
            p1 *= inv;
        }

        float* pb = pbuf[warp][t & 1];
        pb[lane] = p0;
        pb[lane + 32] = p1;
        __syncwarp();
    }

    // ---------------- final: denom = C + log(sum_j p_j * exp(end_j)) ----------------
    float s = p0 * __expf(end_t[lane]) + p1 * __expf(end_t[lane + 32]);
    #pragma unroll
    for (int off = 16; off; off >>= 1)
        s += __shfl_xor_sync(FULL, s, off);

    if (lane == 0) {
        float denom = C + __logf(s);
        g_per_batch[b] = denom - numer;
    }
}

__global__ void crf_reduce_kernel(float* __restrict__ out)
{
    __shared__ float sh[CRF_B];
    int t = threadIdx.x;
    sh[t] = g_per_batch[t];
    __syncthreads();
    #pragma unroll
    for (int s = CRF_B / 2; s > 0; s >>= 1) {
        if (t < s) sh[t] += sh[t + s];
        __syncthreads();
    }
    if (t == 0) out[0] = sh[0] * (1.0f / (float)CRF_B);
}

extern "C" void kernel_launch(void* const* d_in, const int* in_sizes, int n_in,
                              void* d_out, int out_size)
{
    const float* emissions   = (const float*)d_in[0];
    const float* transitions = (const float*)d_in[1];
    const float* start_t     = (const float*)d_in[2];
    const float* end_t       = (const float*)d_in[3];
    const int* tags          = (const int*)d_in[4];
    const int* mask          = (const int*)d_in[5];

    crf_forward_kernel<<<CRF_B / WPB, 32 * WPB>>>(emissions, transitions, start_t, end_t, tags, mask);
    crf_reduce_kernel<<<1, CRF_B>>>((float*)d_out);
}

// round 8
// speedup vs baseline: 1.0357x; 1.0357x over previous
#include <cuda_runtime.h>
#include <cuda_bf16.h>

#define CRF_B 512
#define CRF_T 1024
#define CRF_K 64
#define PAIRS 4                 // batch-pairs per block
#define THREADS (PAIRS * 64)    // 2 warps per batch

__device__ float g_per_batch[CRF_B];

#define PAIR_BAR() asm volatile("bar.sync %0, 64;" :: "r"(pair + 1) : "memory")

__global__ void __launch_bounds__(THREADS, 1) crf_forward_kernel(
    const float* __restrict__ emissions,       // [B, T, K] f32
    const float* __restrict__ transitions,     // [K, K] f32
    const float* __restrict__ start_t,         // [K] f32
    const float* __restrict__ end_t,           // [K] f32
    const int* __restrict__ tags,              // [B, T] int32
    const int* __restrict__ mask)              // [B, T] int32
{
    __shared__ __align__(16) float pbuf[PAIRS][2][CRF_K];  // double-buffered p
    __shared__ float dhalf[PAIRS][2][2];                   // per-warp half-maxes of e
    __shared__ float ssum[PAIRS][2];                       // final half-sums
    __shared__ float numer_s[PAIRS];                       // numerator per pair

    const int warp = threadIdx.x >> 5;
    const int lane = threadIdx.x & 31;
    const int pair = warp >> 1;        // 0..PAIRS-1
    const int half = warp & 1;         // 0: states 0-31, 1: states 32-63
    const int jown = half * 32 + lane; // this lane's output state
    const int b = blockIdx.x * PAIRS + pair;
    const unsigned FULL = 0xffffffffu;

    const float* em = emissions + (size_t)b * CRF_T * CRF_K;
    const int* tg = tags + (size_t)b * CRF_T;
    const int* mk = mask + (size_t)b * CRF_T;

    // ---------------- numerator (warp B of each pair) ----------------
    if (half == 1) {
        float part = 0.f;
        int cnt = 0;
        for (int t = lane; t < CRF_T; t += 32) {
            int m = (mk[t] != 0) ? 1 : 0;
            cnt += m;
            if (t > 0 && m) {
                int tag  = tg[t];
                int ptag = tg[t - 1];
                part += em[t * CRF_K + tag] + transitions[ptag * CRF_K + tag];
            }
        }
        #pragma unroll
        for (int off = 16; off; off >>= 1) {
            part += __shfl_xor_sync(FULL, part, off);
            cnt  += __shfl_xor_sync(FULL, cnt,  off);
        }
        if (lane == 0) {
            int tag0 = tg[0];
            numer_s[pair] = part + em[tag0] + start_t[tag0] + end_t[tg[cnt - 1]];
        }
    }

    // ------- E column for this lane's output state: E[i] = exp(T[i][jown]) -------
    float E[CRF_K];
    #pragma unroll
    for (int i = 0; i < CRF_K; i++)
        E[i] = __expf(transitions[i * CRF_K + jown]);

    // ---------------- init: p = exp(alpha0 - a00), C = a00 ----------------
    float a00 = em[0] + start_t[0];                 // scalar ref, same in both warps
    float p = __expf(em[jown] + start_t[jown] - a00);
    float C = a00;

    // ------- prologue for the (w, delta) pipeline: steps 1 and 2 -------
    float wc, dc, eN, dN = 0.f;
    int mc, mN;
    {
        float e1 = em[CRF_K + jown];
        float e2 = em[2 * CRF_K + jown];
        float h1 = e1, h2 = e2;
        #pragma unroll
        for (int off = 16; off; off >>= 1) {
            h1 = fmaxf(h1, __shfl_xor_sync(FULL, h1, off));
            h2 = fmaxf(h2, __shfl_xor_sync(FULL, h2, off));
        }
        if (lane == 0) {
            dhalf[pair][1][half] = h1;   // slot for t=1 (1&1)
            dhalf[pair][0][half] = h2;   // slot for t=2 (2&1)
        }
        pbuf[pair][0][jown] = p;         // seed p buffer for t=1
        PAIR_BAR();
        float d1 = fmaxf(dhalf[pair][1][0], dhalf[pair][1][1]);
        wc = __expf(e1 - d1);
        dc = d1;
        mc = mk[1];
        eN = e2;
        mN = mk[2];
    }

    for (int t = 1; t < CRF_T; ++t) {
        // ---- off-chain: load e(t+2), half-max, publish ----
        float eP = 0.f;
        int mP = 0;
        if (t + 2 < CRF_T) {
            eP = em[(t + 2) * CRF_K + jown];
            mP = mk[t + 2];
        }
        float hm = eP;
        #pragma unroll
        for (int off = 16; off; off >>= 1)
            hm = fmaxf(hm, __shfl_xor_sync(FULL, hm, off));
        if (lane == 0) dhalf[pair][t & 1][half] = hm;   // slot (t+2)&1 == t&1

        // ---- off-chain: finish w for step t+1 from halves published at t-1 ----
        float dNx = fmaxf(dhalf[pair][(t + 1) & 1][0], dhalf[pair][(t + 1) & 1][1]);
        float wN = __expf(eN - dNx);

        // ---- matvec: s = sum_i p_i * E[i] (full p via broadcast LDS.128) ----
        const float4* pv4 = (const float4*)pbuf[pair][(t - 1) & 1];
        float sa = 0.f, sb = 0.f, sc = 0.f, sd = 0.f;
        #pragma unroll
        for (int q = 0; q < 16; q++) {
            float4 v = pv4[q];
            int i = q * 4;
            sa = fmaf(v.x, E[i],     sa);
            sb = fmaf(v.y, E[i + 1], sb);
            sc = fmaf(v.z, E[i + 2], sc);
            sd = fmaf(v.w, E[i + 3], sd);
        }
        float s = (sa + sb) + (sc + sd);

        // ---- exp-space masked update ----
        bool mm = (mc != 0);
        float np = s * wc;
        p = mm ? np : p;
        C = mm ? C + dc : C;

        // ---- periodic renorm by previous step's p[0] (shared broadcast) ----
        if ((t & 7) == 0) {
            float r = pbuf[pair][(t - 1) & 1][0];
            C += __logf(r);
            p *= __fdividef(1.0f, r);
        }

        pbuf[pair][t & 1][jown] = p;
        PAIR_BAR();

        // rotate pipeline
        wc = wN; dc = dNx; mc = mN;
        eN = eP; mN = mP;
    }

    // ---------------- final: denom = C + log(sum_j p_j * exp(end_j)) ----------------
    float fs = p * __expf(end_t[jown]);
    #pragma unroll
    for (int off = 16; off; off >>= 1)
        fs += __shfl_xor_sync(FULL, fs, off);
    if (lane == 0) ssum[pair][half] = fs;
    PAIR_BAR();

    if (half == 0 && lane == 0) {
        float denom = C + __logf(ssum[pair][0] + ssum[pair][1]);
        g_per_batch[b] = denom - numer_s[pair];
    }
}

__global__ void crf_reduce_kernel(float* __restrict__ out)
{
    __shared__ float sh[CRF_B];
    int t = threadIdx.x;
    sh[t] = g_per_batch[t];
    __syncthreads();
    #pragma unroll
    for (int s = CRF_B / 2; s > 0; s >>= 1) {
        if (t < s) sh[t] += sh[t + s];
        __syncthreads();
    }
    if (t == 0) out[0] = sh[0] * (1.0f / (float)CRF_B);
}

extern "C" void kernel_launch(void* const* d_in, const int* in_sizes, int n_in,
                              void* d_out, int out_size)
{
    const float* emissions   = (const float*)d_in[0];
    const float* transitions = (const float*)d_in[1];
    const float* start_t     = (const float*)d_in[2];
    const float* end_t       = (const float*)d_in[3];
    const int* tags          = (const int*)d_in[4];
    const int* mask          = (const int*)d_in[5];

    crf_forward_kernel<<<CRF_B / PAIRS, THREADS>>>(emissions, transitions, start_t, end_t, tags, mask);
    crf_reduce_kernel<<<1, CRF_B>>>((float*)d_out);
}

// round 9
// speedup vs baseline: 1.1434x; 1.1040x over previous
#include <cuda_runtime.h>
#include <cuda_bf16.h>

#define CRF_B 512
#define CRF_T 1024
#define CRF_K 64
#define WPB 8   // warps per block -> 2 warps per SMSP, 64 CTAs

__device__ float g_per_batch[CRF_B];

__global__ void __launch_bounds__(32 * WPB, 1) crf_forward_kernel(
    const float* __restrict__ emissions,       // [B, T, K] f32
    const float* __restrict__ transitions,     // [K, K] f32
    const float* __restrict__ start_t,         // [K] f32
    const float* __restrict__ end_t,           // [K] f32
    const int* __restrict__ tags,              // [B, T] int32
    const int* __restrict__ mask)              // [B, T] int32
{
    __shared__ __align__(16) float pbuf[WPB][2][CRF_K];

    const int warp = threadIdx.x >> 5;
    const int lane = threadIdx.x & 31;
    const int b = blockIdx.x * WPB + warp;
    const unsigned FULL = 0xffffffffu;

    const float* em = emissions + (size_t)b * CRF_T * CRF_K;
    const int* tg = tags + (size_t)b * CRF_T;
    const int* mk = mask + (size_t)b * CRF_T;

    // ---------------- numerator (gold-path score) ----------------
    float part = 0.f;
    int cnt = 0;
    for (int t = lane; t < CRF_T; t += 32) {
        int m = (mk[t] != 0) ? 1 : 0;
        cnt += m;
        if (t > 0 && m) {
            int tag  = tg[t];
            int ptag = tg[t - 1];
            part += em[t * CRF_K + tag] + transitions[ptag * CRF_K + tag];
        }
    }
    #pragma unroll
    for (int off = 16; off; off >>= 1) {
        part += __shfl_xor_sync(FULL, part, off);
        cnt  += __shfl_xor_sync(FULL, cnt,  off);
    }
    float numer = 0.f;
    if (lane == 0) {
        int tag0 = tg[0];
        numer = part + em[tag0] + start_t[tag0];
        numer += end_t[tg[cnt - 1]];
    }

    // ------- E = exp(transitions), 2 columns per thread in registers -------
    float E0[CRF_K];
    float E1[CRF_K];
    #pragma unroll
    for (int i = 0; i < CRF_K; i++) {
        E0[i] = __expf(transitions[i * CRF_K + lane]);
        E1[i] = __expf(transitions[i * CRF_K + lane + 32]);
    }

    // ---------------- init: p = exp(alpha0 - ref0), C = ref0 ----------------
    float a0 = em[lane]      + start_t[lane];
    float a1 = em[lane + 32] + start_t[lane + 32];
    float r0 = fmaxf(a0, a1);
    #pragma unroll
    for (int off = 16; off; off >>= 1)
        r0 = fmaxf(r0, __shfl_xor_sync(FULL, r0, off));
    float p0 = __expf(a0 - r0);
    float p1 = __expf(a1 - r0);
    float C = r0;

    // ------- distance-2 pipeline (named scalars): (w, delta, mask) -------
    float wc0, wc1, dc, wn0, wn1, dn;
    int mc, mn;
    {
        float e10 = em[CRF_K + lane],     e11 = em[CRF_K + 32 + lane];
        float d1 = fmaxf(e10, e11);
        #pragma unroll
        for (int off = 16; off; off >>= 1)
            d1 = fmaxf(d1, __shfl_xor_sync(FULL, d1, off));
        dc = d1; wc0 = __expf(e10 - d1); wc1 = __expf(e11 - d1);
        mc = mk[1];

        float e20 = em[2 * CRF_K + lane], e21 = em[2 * CRF_K + 32 + lane];
        float d2 = fmaxf(e20, e21);
        #pragma unroll
        for (int off = 16; off; off >>= 1)
            d2 = fmaxf(d2, __shfl_xor_sync(FULL, d2, off));
        dn = d2; wn0 = __expf(e20 - d2); wn1 = __expf(e21 - d2);
        mn = mk[2];
    }

    // seed p buffer for t = 1
    {
        float* pb0 = pbuf[warp][0];
        pb0[lane] = p0;
        pb0[lane + 32] = p1;
        __syncwarp();
    }

    for (int t = 1; t < CRF_T; ++t) {
        // ---- off-chain: load e(t+2), warp-max, exp -> next-next pipeline entry ----
        float ep0 = 0.f, ep1 = 0.f;
        int mp = 0;
        if (t + 2 < CRF_T) {
            ep0 = em[(t + 2) * CRF_K + lane];
            ep1 = em[(t + 2) * CRF_K + 32 + lane];
            mp  = mk[t + 2];
        }
        float dm = fmaxf(ep0, ep1);
        #pragma unroll
        for (int off = 16; off; off >>= 1)
            dm = fmaxf(dm, __shfl_xor_sync(FULL, dm, off));
        float wp0 = __expf(ep0 - dm);
        float wp1 = __expf(ep1 - dm);

        // ---- matvec: s_j = sum_i p_i * E[i][j], 8 accumulators (16-deep chains) ----
        const float4* pv4 = (const float4*)pbuf[warp][(t - 1) & 1];
        float s0a = 0.f, s0b = 0.f, s0c = 0.f, s0d = 0.f;
        float s1a = 0.f, s1b = 0.f, s1c = 0.f, s1d = 0.f;
        #pragma unroll
        for (int q = 0; q < 8; q++) {
            float4 u = pv4[2 * q];
            float4 v = pv4[2 * q + 1];
            int i = q * 8;
            s0a = fmaf(u.x, E0[i],     s0a);
            s0b = fmaf(u.y, E0[i + 1], s0b);
            s0c = fmaf(u.z, E0[i + 2], s0c);
            s0d = fmaf(u.w, E0[i + 3], s0d);
            s0a = fmaf(v.x, E0[i + 4], s0a);
            s0b = fmaf(v.y, E0[i + 5], s0b);
            s0c = fmaf(v.z, E0[i + 6], s0c);
            s0d = fmaf(v.w, E0[i + 7], s0d);
            s1a = fmaf(u.x, E1[i],     s1a);
            s1b = fmaf(u.y, E1[i + 1], s1b);
            s1c = fmaf(u.z, E1[i + 2], s1c);
            s1d = fmaf(u.w, E1[i + 3], s1d);
            s1a = fmaf(v.x, E1[i + 4], s1a);
            s1b = fmaf(v.y, E1[i + 5], s1b);
            s1c = fmaf(v.z, E1[i + 6], s1c);
            s1d = fmaf(v.w, E1[i + 7], s1d);
        }
        float s0 = (s0a + s0b) + (s0c + s0d);
        float s1 = (s1a + s1b) + (s1c + s1d);

        // ---- exp-space masked update: p' = s * w, C += delta ----
        bool mm = (mc != 0);
        float np0 = s0 * wc0;
        float np1 = s1 * wc1;
        p0 = mm ? np0 : p0;
        p1 = mm ? np1 : p1;
        C  = mm ? C + dc : C;

        // ---- periodic renorm (keeps p in fp32 range) ----
        if ((t & 7) == 0) {
            float r = __shfl_sync(FULL, p0, 0);
            C += __logf(r);
            float inv = __fdividef(1.0f, r);
            p0 *= inv;
            p1 *= inv;
        }

        float* pb = pbuf[warp][t & 1];
        pb[lane] = p0;
        pb[lane + 32] = p1;
        __syncwarp();

        // rotate pipeline (all named scalars)
        wc0 = wn0; wc1 = wn1; dc = dn; mc = mn;
        wn0 = wp0; wn1 = wp1; dn = dm; mn = mp;
    }

    // ---------------- final: denom = C + log(sum_j p_j * exp(end_j)) ----------------
    float fs = p0 * __expf(end_t[lane]) + p1 * __expf(end_t[lane + 32]);
    #pragma unroll
    for (int off = 16; off; off >>= 1)
        fs += __shfl_xor_sync(FULL, fs, off);

    if (lane == 0) {
        float denom = C + __logf(fs);
        g_per_batch[b] = denom - numer;
    }
}

__global__ void crf_reduce_kernel(float* __restrict__ out)
{
    __shared__ float sh[CRF_B];
    int t = threadIdx.x;
    sh[t] = g_per_batch[t];
    __syncthreads();
    #pragma unroll
    for (int s = CRF_B / 2; s > 0; s >>= 1) {
        if (t < s) sh[t] += sh[t + s];
        __syncthreads();
    }
    if (t == 0) out[0] = sh[0] * (1.0f / (float)CRF_B);
}

extern "C" void kernel_launch(void* const* d_in, const int* in_sizes, int n_in,
                              void* d_out, int out_size)
{
    const float* emissions   = (const float*)d_in[0];
    const float* transitions = (const float*)d_in[1];
    const float* start_t     = (const float*)d_in[2];
    const float* end_t       = (const float*)d_in[3];
    const int* tags          = (const int*)d_in[4];
    const int* mask          = (const int*)d_in[5];

    crf_forward_kernel<<<CRF_B / WPB, 32 * WPB>>>(emissions, transitions, start_t, end_t, tags, mask);
    crf_reduce_kernel<<<1, CRF_B>>>((float*)d_out);
}

// round 11
// speedup vs baseline: 1.4764x; 1.2912x over previous
#include <cuda_runtime.h>
#include <cuda_bf16.h>

#define CRF_B 512
#define CRF_T 1024
#define CRF_K 64
#define WPB 4   // 128 CTAs, 1 warp per SMSP on 128 SMs

__device__ float g_per_batch[CRF_B];

__global__ void __launch_bounds__(32 * WPB, 1) crf_forward_kernel(
    const float* __restrict__ emissions,       // [B, T, K] f32
    const float* __restrict__ transitions,     // [K, K] f32
    const float* __restrict__ start_t,         // [K] f32
    const float* __restrict__ end_t,           // [K] f32
    const int* __restrict__ tags,              // [B, T] int32
    const int* __restrict__ mask)              // [B, T] int32
{
    __shared__ __align__(16) float pbuf[WPB][2][CRF_K];

    const int warp = threadIdx.x >> 5;
    const int lane = threadIdx.x & 31;
    const int b = blockIdx.x * WPB + warp;
    const unsigned FULL = 0xffffffffu;

    const float* em = emissions + (size_t)b * CRF_T * CRF_K;
    const int* tg = tags + (size_t)b * CRF_T;
    const int* mk = mask + (size_t)b * CRF_T;

    // ---------------- numerator (gold-path score) ----------------
    float part = 0.f;
    int cnt = 0;
    for (int t = lane; t < CRF_T; t += 32) {
        int m = (mk[t] != 0) ? 1 : 0;
        cnt += m;
        if (t > 0 && m) {
            int tag  = tg[t];
            int ptag = tg[t - 1];
            part += em[t * CRF_K + tag] + transitions[ptag * CRF_K + tag];
        }
    }
    #pragma unroll
    for (int off = 16; off; off >>= 1) {
        part += __shfl_xor_sync(FULL, part, off);
        cnt  += __shfl_xor_sync(FULL, cnt,  off);
    }
    float numer = 0.f;
    if (lane == 0) {
        int tag0 = tg[0];
        numer = part + em[tag0] + start_t[tag0];
        numer += end_t[tg[cnt - 1]];
    }

    // ------- E = exp(transitions), 2 columns per thread in registers -------
    float E0[CRF_K];
    float E1[CRF_K];
    #pragma unroll
    for (int i = 0; i < CRF_K; i++) {
        E0[i] = __expf(transitions[i * CRF_K + lane]);
        E1[i] = __expf(transitions[i * CRF_K + lane + 32]);
    }

    // ---------------- init: p = exp(alpha0 - ref0), C = ref0 ----------------
    float a0 = em[lane]      + start_t[lane];
    float a1 = em[lane + 32] + start_t[lane + 32];
    float r0 = fmaxf(a0, a1);
    #pragma unroll
    for (int off = 16; off; off >>= 1)
        r0 = fmaxf(r0, __shfl_xor_sync(FULL, r0, off));
    float p0 = __expf(a0 - r0);
    float p1 = __expf(a1 - r0);
    float C = r0;

    // ------- 3-deep software pipeline, all named scalars -------
    // (wc,dc,mc): cooked, for step t        (current)
    // (wn,dn,mn): cooked, for step t+1
    // (cw0,cw1,cd,cm) produced this iter from raw regs = step t+2
    // (rE0,rE1,rM): raw loads, step t+3
    float wc0, wc1, dc, wn0, wn1, dn;
    int mc, mn;
    float rE0, rE1;
    int rM;
    {
        float e10 = em[CRF_K + lane],     e11 = em[CRF_K + 32 + lane];
        float d1 = fmaxf(e10, e11);
        #pragma unroll
        for (int off = 16; off; off >>= 1)
            d1 = fmaxf(d1, __shfl_xor_sync(FULL, d1, off));
        dc = d1; wc0 = __expf(e10 - d1); wc1 = __expf(e11 - d1);
        mc = mk[1];

        float e20 = em[2 * CRF_K + lane], e21 = em[2 * CRF_K + 32 + lane];
        float d2 = fmaxf(e20, e21);
        #pragma unroll
        for (int off = 16; off; off >>= 1)
            d2 = fmaxf(d2, __shfl_xor_sync(FULL, d2, off));
        dn = d2; wn0 = __expf(e20 - d2); wn1 = __expf(e21 - d2);
        mn = mk[2];

        // raw loads for step 3
        rE0 = em[3 * CRF_K + lane];
        rE1 = em[3 * CRF_K + 32 + lane];
        rM  = mk[3];
    }

    // seed p buffer for t = 1
    {
        float* pb0 = pbuf[warp][0];
        pb0[lane] = p0;
        pb0[lane + 32] = p1;
        __syncwarp();
    }

    for (int t = 1; t < CRF_T; ++t) {
        // ---- (1) issue raw loads for step t+3 FIRST (consumed next iteration) ----
        float nE0 = 0.f, nE1 = 0.f;
        int nM = 0;
        if (t + 3 < CRF_T) {
            nE0 = em[(t + 3) * CRF_K + lane];
            nE1 = em[(t + 3) * CRF_K + 32 + lane];
            nM  = mk[t + 3];
        }

        // ---- (2) cook step t+2 from raw regs loaded LAST iteration ----
        float dm = fmaxf(rE0, rE1);
        #pragma unroll
        for (int off = 16; off; off >>= 1)
            dm = fmaxf(dm, __shfl_xor_sync(FULL, dm, off));
        float cw0 = __expf(rE0 - dm);
        float cw1 = __expf(rE1 - dm);
        int   cm  = rM;

        // ---- (3) matvec: s_j = sum_i p_i * E[i][j], 8 accumulators ----
        const float4* pv4 = (const float4*)pbuf[warp][(t - 1) & 1];
        float s0a = 0.f, s0b = 0.f, s0c = 0.f, s0d = 0.f;
        float s1a = 0.f, s1b = 0.f, s1c = 0.f, s1d = 0.f;
        #pragma unroll
        for (int q = 0; q < 8; q++) {
            float4 u = pv4[2 * q];
            float4 v = pv4[2 * q + 1];
            int i = q * 8;
            s0a = fmaf(u.x, E0[i],     s0a);
            s0b = fmaf(u.y, E0[i + 1], s0b);
            s0c = fmaf(u.z, E0[i + 2], s0c);
            s0d = fmaf(u.w, E0[i + 3], s0d);
            s0a = fmaf(v.x, E0[i + 4], s0a);
            s0b = fmaf(v.y, E0[i + 5], s0b);
            s0c = fmaf(v.z, E0[i + 6], s0c);
            s0d = fmaf(v.w, E0[i + 7], s0d);
            s1a = fmaf(u.x, E1[i],     s1a);
            s1b = fmaf(u.y, E1[i + 1], s1b);
            s1c = fmaf(u.z, E1[i + 2], s1c);
            s1d = fmaf(u.w, E1[i + 3], s1d);
            s1a = fmaf(v.x, E1[i + 4], s1a);
            s1b = fmaf(v.y, E1[i + 5], s1b);
            s1c = fmaf(v.z, E1[i + 6], s1c);
            s1d = fmaf(v.w, E1[i + 7], s1d);
        }
        float s0 = (s0a + s0b) + (s0c + s0d);
        float s1 = (s1a + s1b) + (s1c + s1d);

        // ---- (4) exp-space masked update: p' = s * w, C += delta ----
        bool mm = (mc != 0);
        float np0 = s0 * wc0;
        float np1 = s1 * wc1;
        p0 = mm ? np0 : p0;
        p1 = mm ? np1 : p1;
        C  = mm ? C + dc : C;

        // ---- (5) periodic renorm (keeps p in fp32 range) ----
        if ((t & 15) == 0) {
            float r = __shfl_sync(FULL, p0, 0);
            C += __logf(r);
            float inv = __fdividef(1.0f, r);
            p0 *= inv;
            p1 *= inv;
        }

        // ---- (6) publish p for next step ----
        float* pb = pbuf[warp][t & 1];
        pb[lane] = p0;
        pb[lane + 32] = p1;
        __syncwarp();

        // ---- (7) rotate pipeline (named scalars only) ----
        wc0 = wn0; wc1 = wn1; dc = dn; mc = mn;
        wn0 = cw0; wn1 = cw1; dn = dm; mn = cm;
        rE0 = nE0; rE1 = nE1; rM = nM;
    }

    // ---------------- final: denom = C + log(sum_j p_j * exp(end_j)) ----------------
    float fs = p0 * __expf(end_t[lane]) + p1 * __expf(end_t[lane + 32]);
    #pragma unroll
    for (int off = 16; off; off >>= 1)
        fs += __shfl_xor_sync(FULL, fs, off);

    if (lane == 0) {
        float denom = C + __logf(fs);
        g_per_batch[b] = denom - numer;
    }
}

__global__ void crf_reduce_kernel(float* __restrict__ out)
{
    __shared__ float sh[CRF_B];
    int t = threadIdx.x;
    sh[t] = g_per_batch[t];
    __syncthreads();
    #pragma unroll
    for (int s = CRF_B / 2; s > 0; s >>= 1) {
        if (t < s) sh[t] += sh[t + s];
        __syncthreads();
    }
    if (t == 0) out[0] = sh[0] * (1.0f / (float)CRF_B);
}

extern "C" void kernel_launch(void* const* d_in, const int* in_sizes, int n_in,
                              void* d_out, int out_size)
{
    const float* emissions   = (const float*)d_in[0];
    const float* transitions = (const float*)d_in[1];
    const float* start_t     = (const float*)d_in[2];
    const float* end_t       = (const float*)d_in[3];
    const int* tags          = (const int*)d_in[4];
    const int* mask          = (const int*)d_in[5];

    crf_forward_kernel<<<CRF_B / WPB, 32 * WPB>>>(emissions, transitions, start_t, end_t, tags, mask);
    crf_reduce_kernel<<<1, CRF_B>>>((float*)d_out);
}